// round 10
// baseline (speedup 1.0000x reference)
#include <cuda_runtime.h>
#include <cuda_bf16.h>
#include <cstdint>

// Problem constants
#define M_ROWS  200000      // BATCH * SIM_T
#define K_DIM   784
#define N1      100
#define T_STEPS 2000
#define BATCH   100
#define N2      10

// Scratch (padded so scan prefetch queues need no bounds checks)
__device__ float g_z1[(size_t)(M_ROWS + 8) * N1];           // 80 MB
__device__ float g_T1[(size_t)M_ROWS * N1];                 // 80 MB
__device__ float g_z2t[(size_t)BATCH * N2 * T_STEPS + 16];  // 8 MB
__device__ __align__(16) __nv_bfloat16 g_W1h[112 * K_DIM];
__device__ __align__(16) __nv_bfloat16 g_W1l[112 * K_DIM];

// ---------------------------------------------------------------------------
// helpers
// ---------------------------------------------------------------------------
__device__ __forceinline__ unsigned pack_bf16x2(float fhi, float flo) {
    unsigned r;
    asm("cvt.rn.bf16x2.f32 %0, %1, %2;" : "=r"(r) : "f"(fhi), "f"(flo));
    return r;
}
__device__ __forceinline__ void mma_bf16(float* c, const unsigned* a,
                                         unsigned b0, unsigned b1) {
    asm("mma.sync.aligned.m16n8k16.row.col.f32.bf16.bf16.f32 "
        "{%0,%1,%2,%3}, {%4,%5,%6,%7}, {%8,%9}, {%0,%1,%2,%3};"
        : "+f"(c[0]), "+f"(c[1]), "+f"(c[2]), "+f"(c[3])
        : "r"(a[0]), "r"(a[1]), "r"(a[2]), "r"(a[3]), "r"(b0), "r"(b1));
}

// ---------------------------------------------------------------------------
// K0: convert W1 -> bf16 hi/lo, padded to 112 rows
// ---------------------------------------------------------------------------
__global__ void w1_convert_kernel(const float* __restrict__ W1) {
    int idx = blockIdx.x * 256 + threadIdx.x;
    if (idx >= 112 * K_DIM) return;
    int r = idx / K_DIM;
    float w = (r < N1) ? W1[idx] : 0.f;
    __nv_bfloat16 hb = __float2bfloat16_rn(w);
    float hf = __bfloat162float(hb);
    g_W1h[idx] = hb;
    g_W1l[idx] = __float2bfloat16_rn(w - hf);
}

// ---------------------------------------------------------------------------
// K1: tensor-core GEMM  z1 = A @ W1^T  (bf16 3-split, fp32 acc) — R4 version
// ---------------------------------------------------------------------------
#define NSTAGE 49

__global__ void __launch_bounds__(256, 2)
gemm_z1_tc(const float* __restrict__ A) {
    __shared__ unsigned Ah[2][128 * 8];
    __shared__ unsigned Al[2][128 * 8];
    __shared__ unsigned Bh[2][112 * 8];
    __shared__ unsigned Bl[2][112 * 8];

    const int tid  = threadIdx.x;
    const int warp = tid >> 5, lane = tid & 31;
    const int g    = lane >> 2, tig = lane & 3;
    const int wm   = (warp >> 1) * 32;
    const int wn   = (warp & 1) * 56;
    const int row0 = blockIdx.x * 128;

    float acc[2][7][4];
#pragma unroll
    for (int i = 0; i < 2; i++)
#pragma unroll
        for (int j = 0; j < 7; j++)
#pragma unroll
            for (int q = 0; q < 4; q++) acc[i][j][q] = 0.f;

    float4 va[2];
    unsigned vbh[4], vbl[4];

    auto ldg_stage = [&](int s) {
        int k0 = s * 16;
#pragma unroll
        for (int i = 0; i < 2; i++) {
            int idx = tid + i * 256;
            int r = idx >> 2, q = idx & 3;
            int gr = row0 + r;
            va[i] = (gr < M_ROWS)
                  ? *(const float4*)(A + (size_t)gr * K_DIM + k0 + 4 * q)
                  : make_float4(0.f, 0.f, 0.f, 0.f);
        }
#pragma unroll
        for (int i = 0; i < 4; i++) {
            int idx = tid + i * 256;
            if (idx < 896) {
                int r = idx >> 3, j = idx & 7;
                size_t off = (size_t)r * (K_DIM / 2) + (k0 >> 1) + j;
                vbh[i] = ((const unsigned*)g_W1h)[off];
                vbl[i] = ((const unsigned*)g_W1l)[off];
            }
        }
    };
    auto sts_stage = [&](int buf) {
#pragma unroll
        for (int i = 0; i < 2; i++) {
            int idx = tid + i * 256;
            int r = idx >> 2, q = idx & 3;
            float4 v = va[i];
            unsigned h0 = pack_bf16x2(v.y, v.x);
            unsigned h1 = pack_bf16x2(v.w, v.z);
            float f0h = __uint_as_float(h0 << 16);
            float f1h = __uint_as_float(h0 & 0xffff0000u);
            float f2h = __uint_as_float(h1 << 16);
            float f3h = __uint_as_float(h1 & 0xffff0000u);
            unsigned l0 = pack_bf16x2(v.y - f1h, v.x - f0h);
            unsigned l1 = pack_bf16x2(v.w - f3h, v.z - f2h);
            int sw = r & 7;
            Ah[buf][r * 8 + ((2 * q)     ^ sw)] = h0;
            Ah[buf][r * 8 + ((2 * q + 1) ^ sw)] = h1;
            Al[buf][r * 8 + ((2 * q)     ^ sw)] = l0;
            Al[buf][r * 8 + ((2 * q + 1) ^ sw)] = l1;
        }
#pragma unroll
        for (int i = 0; i < 4; i++) {
            int idx = tid + i * 256;
            if (idx < 896) {
                int r = idx >> 3, j = idx & 7;
                Bh[buf][r * 8 + (j ^ (r & 7))] = vbh[i];
                Bl[buf][r * 8 + (j ^ (r & 7))] = vbl[i];
            }
        }
    };

    ldg_stage(0);
    sts_stage(0);
    __syncthreads();

#pragma unroll 1
    for (int s = 0; s < NSTAGE; s++) {
        if (s + 1 < NSTAGE) ldg_stage(s + 1);

        const int buf = s & 1;
        unsigned a_h[2][4], a_l[2][4];
#pragma unroll
        for (int mt = 0; mt < 2; mt++) {
            int r0 = wm + mt * 16 + g, r1 = r0 + 8;
            int s0 = r0 & 7, s1 = r1 & 7;
            a_h[mt][0] = Ah[buf][r0 * 8 + (tig ^ s0)];
            a_h[mt][1] = Ah[buf][r1 * 8 + (tig ^ s1)];
            a_h[mt][2] = Ah[buf][r0 * 8 + ((tig + 4) ^ s0)];
            a_h[mt][3] = Ah[buf][r1 * 8 + ((tig + 4) ^ s1)];
            a_l[mt][0] = Al[buf][r0 * 8 + (tig ^ s0)];
            a_l[mt][1] = Al[buf][r1 * 8 + (tig ^ s1)];
            a_l[mt][2] = Al[buf][r0 * 8 + ((tig + 4) ^ s0)];
            a_l[mt][3] = Al[buf][r1 * 8 + ((tig + 4) ^ s1)];
        }
#pragma unroll
        for (int nt = 0; nt < 7; nt++) {
            int n = wn + nt * 8 + g;
            int sn = n & 7;
            unsigned b0h = Bh[buf][n * 8 + (tig ^ sn)];
            unsigned b1h = Bh[buf][n * 8 + ((tig + 4) ^ sn)];
            unsigned b0l = Bl[buf][n * 8 + (tig ^ sn)];
            unsigned b1l = Bl[buf][n * 8 + ((tig + 4) ^ sn)];
#pragma unroll
            for (int mt = 0; mt < 2; mt++) {
                mma_bf16(acc[mt][nt], a_h[mt], b0h, b1h);
                mma_bf16(acc[mt][nt], a_h[mt], b0l, b1l);
                mma_bf16(acc[mt][nt], a_l[mt], b0h, b1h);
            }
        }

        if (s + 1 < NSTAGE) sts_stage((s + 1) & 1);
        __syncthreads();
    }

#pragma unroll
    for (int mt = 0; mt < 2; mt++) {
#pragma unroll
        for (int nt = 0; nt < 7; nt++) {
            int c = wn + nt * 8 + 2 * tig;
            if (c >= 99) continue;
            int r0g = row0 + wm + mt * 16 + g;
            if (r0g < M_ROWS) {
                float2 v = make_float2(acc[mt][nt][0], acc[mt][nt][1]);
                *(float2*)(g_z1 + (size_t)r0g * N1 + c) = v;
            }
            if (r0g + 8 < M_ROWS) {
                float2 v = make_float2(acc[mt][nt][2], acc[mt][nt][3]);
                *(float2*)(g_z1 + (size_t)(r0g + 8) * N1 + c) = v;
            }
        }
    }
}

// ---------------------------------------------------------------------------
// HH step — 2 EX2 + 4 RCP per step.
//   uN = exp((Vn-25)/9) via EX2; uM = uN * e^{20/3} (constant-folded);
//   w  = exp((Vn+90)/12) via EX2;
//   sigmoid((Vn-20)/3) = uN^3 / (uN^3 + e^{-5/3})  (no extra EX2).
// ---------------------------------------------------------------------------
__device__ __forceinline__ float ex2a(float x) {
    float r; asm("ex2.approx.f32 %0, %1;" : "=f"(r) : "f"(x)); return r;
}
__device__ __forceinline__ float rcpa(float x) {
    float r; asm("rcp.approx.f32 %0, %1;" : "=f"(r) : "f"(x)); return r;
}

#define L9    0.1602994489863f     // log2(e)/9
#define L12   0.1202245867397f     // log2(e)/12
#define BH_C  0.0023508962f        // 0.25*exp(-56/12)
#define S0V   9.357622969e-14f     // sigmoid((-70-20)/3)
#define C_M   785.7722f            // exp(60/9)
#define C_MA  143.01054f           // 0.182 * C_M
#define C_MB  1.4301054f           // 0.00182 * C_M
#define C_S   0.18887565f          // exp(-5/3)

__device__ __forceinline__ float hh_step_t(float zk, float& V, float& m, float& n, float& h) {
    // ---- V update ----
    float mm   = m * m;
    float pow1 = 40.f * (mm * m) * h;
    float nn   = n * n;
    float pow2 = 35.f * (nn * nn);
    float Gs = 0.005f * (pow1 + pow2 + 0.3f);
    float E  = fmaf(pow1, 55.f, fmaf(pow2, -77.f, -19.5f));
    float num = fmaf(V, (1.f - Gs), 0.01f * (E + 1.5f + zk));
    float Vn = num * rcpa(1.f + Gs);

    // ---- both EX2 issued together ----
    float dN = Vn - 25.f;
    float uN = ex2a(dN * L9);
    float w  = ex2a((Vn + 90.f) * L12);
    float dM = Vn + 35.f;

    // ---- FMA work (overlaps EX2 latency) ----
    // N gate pieces
    float um1N = uN - 1.f;
    float sN = 0.005f * dN * fmaf(0.02f, uN, 0.002f);
    // M gate pieces (uM = C_M * uN, constants folded)
    float um1M = fmaf(C_M, uN, -1.f);
    float sM = 0.005f * dM * fmaf(C_MA, uN, 0.124f);
    // H gate pieces
    float sH = fmaf(0.005f * BH_C, w * w, 0.00125f);
    // sigmoid pieces
    float uN3 = (uN * uN) * uN;

    // ---- batch all RCP ----
    float rN = rcpa(um1N + sN);
    float rM = rcpa(um1M + sM);
    float rH = rcpa(w + sH);
    float rS = rcpa(uN3 + C_S);

    // ---- finals ----
    float nN = fmaf(0.0002f * dN, uN, (um1N - sN) * n) * rN;
    float mN = fmaf(C_MB * dM, uN, (um1M - sM) * m) * rM;
    float hN = fmaf(w - sH, h, 0.0025f) * rH;
    float T  = uN3 * rS;

    if (Vn == 25.f)  nN = fmaf(0.99901f, n, 0.0018f) * (1.f / 1.00099f);
    if (Vn == -35.f) mN = fmaf(0.98623f, m, 0.01638f) * (1.f / 1.01377f);

    m = mN; n = nN; h = hN;
    V = Vn;
    return T;
}

// ---------------------------------------------------------------------------
// K2: layer-1 scan. One thread per chain; exactly 1999 steps, no predication.
// ---------------------------------------------------------------------------
__global__ void __launch_bounds__(128, 1)
hh_layer1_kernel() {
    const int idx = blockIdx.x * 128 + threadIdx.x;
    if (idx >= BATCH * N1) return;
    const int b = idx / N1;
    const int c = idx - b * N1;

    const float* zl = g_z1 + (size_t)b * T_STEPS * N1 + c;
    float*       ts = g_T1 + (size_t)b * T_STEPS * N1 + c;

    float V = -70.f, m = 0.f, n = 0.f, h = 1.f;
    ts[0] = S0V;
    ts += N1;

    float p0 = zl[0];
    float p1 = zl[N1];
    float p2 = zl[2 * N1];
    float p3 = zl[3 * N1];
    zl += 4 * N1;

    // 1999 steps = 249*8 + 7 (prefetch beyond T_STEPS hits the +8 row pad)
#pragma unroll 1
    for (int s8 = 0; s8 < 1992; s8 += 8) {
#pragma unroll
        for (int j = 0; j < 8; j++) {
            float zc = p0;
            p0 = p1; p1 = p2; p2 = p3; p3 = *zl; zl += N1;
            *ts = hh_step_t(zc, V, m, n, h);
            ts += N1;
        }
    }
#pragma unroll
    for (int j = 0; j < 7; j++) {
        float zc = p0;
        p0 = p1; p1 = p2; p2 = p3; p3 = *zl; zl += N1;
        *ts = hh_step_t(zc, V, m, n, h);
        ts += N1;
    }
}

// ---------------------------------------------------------------------------
// K3: z2t[b*10+o][t] = sum_k T1[b][t][k] * W2[o][k]  (R4 version)
// ---------------------------------------------------------------------------
__global__ void __launch_bounds__(256, 4)
z2_kernel(const float* __restrict__ W2) {
    __shared__ float W2s[N1][12];

    const int tid = threadIdx.x;
    for (int i = tid; i < N1 * 12; i += 256) {
        int k = i / 12, o = i - k * 12;
        W2s[k][o] = (o < N2) ? W2[o * N1 + k] : 0.f;
    }
    __syncthreads();

    const int row = blockIdx.x * 256 + tid;
    if (row >= M_ROWS) return;
    const int b = row / T_STEPS;
    const int t = row - b * T_STEPS;

    const float4* tr = (const float4*)(g_T1 + (size_t)row * N1);
    float acc[12];
#pragma unroll
    for (int o = 0; o < 12; o++) acc[o] = 0.f;

#pragma unroll 5
    for (int k4 = 0; k4 < 25; k4++) {
        float4 tv = tr[k4];
        const float* tf = &tv.x;
#pragma unroll
        for (int kk = 0; kk < 4; kk++) {
            int k = k4 * 4 + kk;
            float4 w0 = *(const float4*)&W2s[k][0];
            float4 w1 = *(const float4*)&W2s[k][4];
            float4 w2 = *(const float4*)&W2s[k][8];
            float f = tf[kk];
            acc[0] = fmaf(f, w0.x, acc[0]);  acc[1] = fmaf(f, w0.y, acc[1]);
            acc[2] = fmaf(f, w0.z, acc[2]);  acc[3] = fmaf(f, w0.w, acc[3]);
            acc[4] = fmaf(f, w1.x, acc[4]);  acc[5] = fmaf(f, w1.y, acc[5]);
            acc[6] = fmaf(f, w1.z, acc[6]);  acc[7] = fmaf(f, w1.w, acc[7]);
            acc[8] = fmaf(f, w2.x, acc[8]);  acc[9] = fmaf(f, w2.y, acc[9]);
        }
    }
#pragma unroll
    for (int o = 0; o < N2; o++)
        g_z2t[((size_t)b * N2 + o) * T_STEPS + t] = acc[o];
}

// ---------------------------------------------------------------------------
// K4: layer-2 scan. One thread per chain; 1999 steps, no predication.
// ---------------------------------------------------------------------------
__global__ void __launch_bounds__(128, 1)
hh_layer2_kernel(float* __restrict__ out) {
    const int idx = blockIdx.x * 128 + threadIdx.x;
    if (idx >= BATCH * N2) return;
    const int b = idx / N2;
    const int o = idx - b * N2;

    const float* zl = g_z2t + (size_t)idx * T_STEPS;
    float* os = out + (size_t)b * T_STEPS * N2 + o;

    float V = -70.f, m = 0.f, n = 0.f, h = 1.f;
    os[0] = S0V;
    os += N2;

    float p0 = zl[0];
    float p1 = zl[1];
    float p2 = zl[2];
    float p3 = zl[3];
    zl += 4;

#pragma unroll 1
    for (int s8 = 0; s8 < 1992; s8 += 8) {
#pragma unroll
        for (int j = 0; j < 8; j++) {
            float zc = p0;
            p0 = p1; p1 = p2; p2 = p3; p3 = *zl; zl++;
            *os = hh_step_t(zc, V, m, n, h);
            os += N2;
        }
    }
#pragma unroll
    for (int j = 0; j < 7; j++) {
        float zc = p0;
        p0 = p1; p1 = p2; p2 = p3; p3 = *zl; zl++;
        *os = hh_step_t(zc, V, m, n, h);
        os += N2;
    }
}

// ---------------------------------------------------------------------------
extern "C" void kernel_launch(void* const* d_in, const int* in_sizes, int n_in,
                              void* d_out, int out_size) {
    const float* batch = (const float*)d_in[0];   // (100, 2000, 784)
    const float* W1    = (const float*)d_in[1];   // (100, 784)
    const float* W2    = (const float*)d_in[2];   // (10, 100)
    float* out = (float*)d_out;                   // (100, 2000, 10)

    w1_convert_kernel<<<(112 * K_DIM + 255) / 256, 256>>>(W1);
    gemm_z1_tc<<<(M_ROWS + 127) / 128, 256>>>(batch);
    hh_layer1_kernel<<<(BATCH * N1 + 127) / 128, 128>>>();
    z2_kernel<<<(M_ROWS + 255) / 256, 256>>>(W2);
    hh_layer2_kernel<<<(BATCH * N2 + 127) / 128, 128>>>(out);
}

// round 11
// speedup vs baseline: 1.2568x; 1.2568x over previous
#include <cuda_runtime.h>
#include <cuda_bf16.h>
#include <cstdint>

// Problem constants
#define M_ROWS  200000      // BATCH * SIM_T
#define K_DIM   784
#define N1      100
#define T_STEPS 2000
#define BATCH   100
#define N2      10
#define NCHUNKS 1563        // ceil(200000/128)

// Scratch.
// g_z1 layout: [t][batch][c]  (row r' = t*100 + b, 100 floats each).
// Padded to t=2008 so the scan prefetch queue never needs guards.
__device__ float g_z1[(size_t)2008 * BATCH * N1];           // 80 MB
__device__ float g_T1[(size_t)M_ROWS * N1];                 // 80 MB  [b][t][c]
__device__ float g_z2t[(size_t)BATCH * N2 * T_STEPS + 16];  // 8 MB
__device__ int   g_flag[1600];                              // per-chunk done flags
__device__ __align__(16) __nv_bfloat16 g_W1h[112 * K_DIM];
__device__ __align__(16) __nv_bfloat16 g_W1l[112 * K_DIM];

// ---------------------------------------------------------------------------
// helpers
// ---------------------------------------------------------------------------
__device__ __forceinline__ unsigned pack_bf16x2(float fhi, float flo) {
    unsigned r;
    asm("cvt.rn.bf16x2.f32 %0, %1, %2;" : "=r"(r) : "f"(fhi), "f"(flo));
    return r;
}
__device__ __forceinline__ void mma_bf16(float* c, const unsigned* a,
                                         unsigned b0, unsigned b1) {
    asm("mma.sync.aligned.m16n8k16.row.col.f32.bf16.bf16.f32 "
        "{%0,%1,%2,%3}, {%4,%5,%6,%7}, {%8,%9}, {%0,%1,%2,%3};"
        : "+f"(c[0]), "+f"(c[1]), "+f"(c[2]), "+f"(c[3])
        : "r"(a[0]), "r"(a[1]), "r"(a[2]), "r"(a[3]), "r"(b0), "r"(b1));
}

// ---------------------------------------------------------------------------
// K0: convert W1 -> bf16 hi/lo (112 rows) + reset chunk flags
// ---------------------------------------------------------------------------
__global__ void w1_convert_kernel(const float* __restrict__ W1) {
    int idx = blockIdx.x * 256 + threadIdx.x;
    if (idx < 1600) g_flag[idx] = 0;
    if (idx >= 112 * K_DIM) return;
    int r = idx / K_DIM;
    float w = (r < N1) ? W1[idx] : 0.f;
    __nv_bfloat16 hb = __float2bfloat16_rn(w);
    float hf = __bfloat162float(hb);
    g_W1h[idx] = hb;
    g_W1l[idx] = __float2bfloat16_rn(w - hf);
}

// ---------------------------------------------------------------------------
// HH step math (exact round-9 version: 4 EX2 batched, 4 RCP batched)
// ---------------------------------------------------------------------------
__device__ __forceinline__ float ex2a(float x) {
    float r; asm("ex2.approx.f32 %0, %1;" : "=f"(r) : "f"(x)); return r;
}
__device__ __forceinline__ float rcpa(float x) {
    float r; asm("rcp.approx.f32 %0, %1;" : "=f"(r) : "f"(x)); return r;
}

#define L9   0.1602994489863f
#define L12  0.1202245867397f
#define L3   0.4808983469589f
#define BH_C 0.0023508962f
#define S0V  9.357622969e-14f

__device__ __forceinline__ float hh_step_t(float zk, float& V, float& m, float& n, float& h) {
    float mm   = m * m;
    float pow1 = 40.f * (mm * m) * h;
    float nn   = n * n;
    float pow2 = 35.f * (nn * nn);
    float Gs = 0.005f * (pow1 + pow2 + 0.3f);
    float E  = fmaf(pow1, 55.f, fmaf(pow2, -77.f, -19.5f));
    float num = fmaf(V, (1.f - Gs), 0.01f * (E + 1.5f + zk));
    float Vn = num * rcpa(1.f + Gs);

    float dM = Vn + 35.f;
    float dN = Vn - 25.f;
    float uM = ex2a(dM * L9);
    float uN = ex2a(dN * L9);
    float w  = ex2a((Vn + 90.f) * L12);
    float eS = ex2a((20.f - Vn) * L3);

    float um1M = uM - 1.f;
    float sM = 0.005f * dM * fmaf(0.182f, uM, 0.124f);
    float um1N = uN - 1.f;
    float sN = 0.005f * dN * fmaf(0.02f, uN, 0.002f);
    float sH = fmaf(0.005f * BH_C, w * w, 0.00125f);

    float rM = rcpa(um1M + sM);
    float rN = rcpa(um1N + sN);
    float rH = rcpa(w + sH);
    float rS = rcpa(1.f + eS);

    float mN = fmaf(0.00182f * dM, uM, (um1M - sM) * m) * rM;
    float nN = fmaf(0.0002f * dN, uN, (um1N - sN) * n) * rN;
    float hN = fmaf(w - sH, h, 0.0025f) * rH;

    if (Vn == 25.f)  nN = fmaf(0.99901f, n, 0.0018f) * (1.f / 1.00099f);
    if (Vn == -35.f) mN = fmaf(0.98623f, m, 0.01638f) * (1.f / 1.01377f);

    m = mN; n = nN; h = hN;
    V = Vn;
    return rS;
}

// ---------------------------------------------------------------------------
// wait until chunk flags [clo, chi] are all set (warp-parallel volatile poll)
// ---------------------------------------------------------------------------
__device__ __forceinline__ void wait_chunks(int clo, int chi) {
    const int lane = threadIdx.x & 31;
    for (int base = clo; base <= chi; base += 32) {
        int cid = min(base + lane, chi);
        while (__any_sync(0xffffffffu, ((volatile int*)g_flag)[cid] == 0))
            __nanosleep(64);
    }
    __threadfence();
}

// ---------------------------------------------------------------------------
// K1: FUSED gemm + layer-1 scan.
//   blocks 0..99       : layer-1 scan for batch blk (threads 0-99 compute,
//                        0-127 participate in flag polls).
//   blocks 100..1662   : GEMM chunk (blk-100): z1 rows [chunk*128, +128) in
//                        r' = t*100+b space; sets g_flag[chunk] when done.
// z1 is produced in t-order, so the scans track the GEMM and finish ~10us
// after it instead of 270us after.
// ---------------------------------------------------------------------------
#define NSTAGE 49

__global__ void __launch_bounds__(256, 2)
fused_gemm_l1(const float* __restrict__ A) {
    __shared__ unsigned Ahs[2][128 * 8];
    __shared__ unsigned Als[2][128 * 8];
    __shared__ unsigned Bhs[2][112 * 8];
    __shared__ unsigned Bls[2][112 * 8];

    const int blk = blockIdx.x;
    const int tid = threadIdx.x;

    if (blk < BATCH) {
        // ================= layer-1 scan, batch blk =================
        if (tid >= 128) return;
        const int b = blk;
        const int c = tid;
        const bool act = (c < N1);

        // z1[t][b][c] address: t*10000 + b*100 + c
        const float* zl = g_z1 + (size_t)b * N1 + c;
        float* ts = g_T1 + (size_t)b * T_STEPS * N1 + c;

        float V = -70.f, m = 0.f, n = 0.f, h = 1.f;
        float p0 = 0.f, p1 = 0.f, p2 = 0.f, p3 = 0.f;

        wait_chunks(0, 3);                      // rows t=0..3
        if (act) {
            ts[0] = S0V;
            p0 = zl[0];
            p1 = zl[10000];
            p2 = zl[20000];
            p3 = zl[30000];
        }
        ts += N1;
        zl += 40000;

        int s = 0;
#pragma unroll 1
        for (int w = 0; w < 40; w++) {
            int tlo = w * 50 + 4;
            int thi = min(w * 50 + 53, T_STEPS - 1);
            if (tlo <= T_STEPS - 1)
                wait_chunks((tlo * 100) / 128, (thi * 100 + 99) / 128);
            const int steps = (w == 39) ? 49 : 50;
            if (act) {
#pragma unroll 1
                for (int j2 = 0; j2 < steps / 2; j2++) {
#pragma unroll
                    for (int j = 0; j < 2; j++) {
                        float zc = p0;
                        p0 = p1; p1 = p2; p2 = p3; p3 = *zl; zl += 10000;
                        *ts = hh_step_t(zc, V, m, n, h);
                        ts += N1;
                    }
                }
                if (steps & 1) {
                    float zc = p0;
                    p0 = p1; p1 = p2; p2 = p3; p3 = *zl; zl += 10000;
                    *ts = hh_step_t(zc, V, m, n, h);
                    ts += N1;
                }
            }
            s += steps;
        }
        return;
    }

    // ================= GEMM chunk =================
    const int chunk = blk - BATCH;
    const int row0  = chunk * 128;

    const int warp = tid >> 5, lane = tid & 31;
    const int g    = lane >> 2, tig = lane & 3;
    const int wm   = (warp >> 1) * 32;
    const int wn   = (warp & 1) * 56;

    // per-thread A row pointers (r' = t*100+b -> A row b*2000+t)
    const float* aptr[2];
    bool av[2];
    {
#pragma unroll
        for (int i = 0; i < 2; i++) {
            int idx = tid + i * 256;
            int rp = row0 + (idx >> 2);
            av[i] = rp < M_ROWS;
            int rc = av[i] ? rp : 0;
            int t = rc / 100;
            int bb = rc - t * 100;
            aptr[i] = A + (size_t)(bb * 2000 + t) * K_DIM + (idx & 3) * 4;
        }
    }

    float acc[2][7][4];
#pragma unroll
    for (int i = 0; i < 2; i++)
#pragma unroll
        for (int j = 0; j < 7; j++)
#pragma unroll
            for (int q = 0; q < 4; q++) acc[i][j][q] = 0.f;

    float4 va[2];
    unsigned vbh[4], vbl[4];

    auto ldg_stage = [&](int s) {
        int k0 = s * 16;
#pragma unroll
        for (int i = 0; i < 2; i++)
            va[i] = av[i] ? *(const float4*)(aptr[i] + k0)
                          : make_float4(0.f, 0.f, 0.f, 0.f);
#pragma unroll
        for (int i = 0; i < 4; i++) {
            int idx = tid + i * 256;
            if (idx < 896) {
                int r = idx >> 3, j = idx & 7;
                size_t off = (size_t)r * (K_DIM / 2) + (k0 >> 1) + j;
                vbh[i] = ((const unsigned*)g_W1h)[off];
                vbl[i] = ((const unsigned*)g_W1l)[off];
            }
        }
    };
    auto sts_stage = [&](int buf) {
#pragma unroll
        for (int i = 0; i < 2; i++) {
            int idx = tid + i * 256;
            int r = idx >> 2, q = idx & 3;
            float4 v = va[i];
            unsigned h0 = pack_bf16x2(v.y, v.x);
            unsigned h1 = pack_bf16x2(v.w, v.z);
            float f0h = __uint_as_float(h0 << 16);
            float f1h = __uint_as_float(h0 & 0xffff0000u);
            float f2h = __uint_as_float(h1 << 16);
            float f3h = __uint_as_float(h1 & 0xffff0000u);
            unsigned l0 = pack_bf16x2(v.y - f1h, v.x - f0h);
            unsigned l1 = pack_bf16x2(v.w - f3h, v.z - f2h);
            int sw = r & 7;
            Ahs[buf][r * 8 + ((2 * q)     ^ sw)] = h0;
            Ahs[buf][r * 8 + ((2 * q + 1) ^ sw)] = h1;
            Als[buf][r * 8 + ((2 * q)     ^ sw)] = l0;
            Als[buf][r * 8 + ((2 * q + 1) ^ sw)] = l1;
        }
#pragma unroll
        for (int i = 0; i < 4; i++) {
            int idx = tid + i * 256;
            if (idx < 896) {
                int r = idx >> 3, j = idx & 7;
                Bhs[buf][r * 8 + (j ^ (r & 7))] = vbh[i];
                Bls[buf][r * 8 + (j ^ (r & 7))] = vbl[i];
            }
        }
    };

    ldg_stage(0);
    sts_stage(0);
    __syncthreads();

#pragma unroll 1
    for (int s = 0; s < NSTAGE; s++) {
        if (s + 1 < NSTAGE) ldg_stage(s + 1);

        const int buf = s & 1;
        unsigned a_h[2][4], a_l[2][4];
#pragma unroll
        for (int mt = 0; mt < 2; mt++) {
            int r0 = wm + mt * 16 + g, r1 = r0 + 8;
            int s0 = r0 & 7, s1 = r1 & 7;
            a_h[mt][0] = Ahs[buf][r0 * 8 + (tig ^ s0)];
            a_h[mt][1] = Ahs[buf][r1 * 8 + (tig ^ s1)];
            a_h[mt][2] = Ahs[buf][r0 * 8 + ((tig + 4) ^ s0)];
            a_h[mt][3] = Ahs[buf][r1 * 8 + ((tig + 4) ^ s1)];
            a_l[mt][0] = Als[buf][r0 * 8 + (tig ^ s0)];
            a_l[mt][1] = Als[buf][r1 * 8 + (tig ^ s1)];
            a_l[mt][2] = Als[buf][r0 * 8 + ((tig + 4) ^ s0)];
            a_l[mt][3] = Als[buf][r1 * 8 + ((tig + 4) ^ s1)];
        }
#pragma unroll
        for (int nt = 0; nt < 7; nt++) {
            int n = wn + nt * 8 + g;
            int sn = n & 7;
            unsigned b0h = Bhs[buf][n * 8 + (tig ^ sn)];
            unsigned b1h = Bhs[buf][n * 8 + ((tig + 4) ^ sn)];
            unsigned b0l = Bls[buf][n * 8 + (tig ^ sn)];
            unsigned b1l = Bls[buf][n * 8 + ((tig + 4) ^ sn)];
#pragma unroll
            for (int mt = 0; mt < 2; mt++) {
                mma_bf16(acc[mt][nt], a_h[mt], b0h, b1h);
                mma_bf16(acc[mt][nt], a_h[mt], b0l, b1l);
                mma_bf16(acc[mt][nt], a_l[mt], b0h, b1h);
            }
        }

        if (s + 1 < NSTAGE) sts_stage((s + 1) & 1);
        __syncthreads();
    }

#pragma unroll
    for (int mt = 0; mt < 2; mt++) {
#pragma unroll
        for (int nt = 0; nt < 7; nt++) {
            int c = wn + nt * 8 + 2 * tig;
            if (c >= 99) continue;
            int r0g = row0 + wm + mt * 16 + g;
            if (r0g < M_ROWS) {
                float2 v = make_float2(acc[mt][nt][0], acc[mt][nt][1]);
                *(float2*)(g_z1 + (size_t)r0g * N1 + c) = v;
            }
            if (r0g + 8 < M_ROWS) {
                float2 v = make_float2(acc[mt][nt][2], acc[mt][nt][3]);
                *(float2*)(g_z1 + (size_t)(r0g + 8) * N1 + c) = v;
            }
        }
    }

    // publish chunk
    __threadfence();
    __syncthreads();
    if (tid == 0) atomicExch(&g_flag[chunk], 1);
}

// ---------------------------------------------------------------------------
// K3: z2t[b*10+o][t] = sum_k T1[b][t][k] * W2[o][k]  (unchanged)
// ---------------------------------------------------------------------------
__global__ void __launch_bounds__(256, 4)
z2_kernel(const float* __restrict__ W2) {
    __shared__ float W2s[N1][12];

    const int tid = threadIdx.x;
    for (int i = tid; i < N1 * 12; i += 256) {
        int k = i / 12, o = i - k * 12;
        W2s[k][o] = (o < N2) ? W2[o * N1 + k] : 0.f;
    }
    __syncthreads();

    const int row = blockIdx.x * 256 + tid;
    if (row >= M_ROWS) return;
    const int b = row / T_STEPS;
    const int t = row - b * T_STEPS;

    const float4* tr = (const float4*)(g_T1 + (size_t)row * N1);
    float acc[12];
#pragma unroll
    for (int o = 0; o < 12; o++) acc[o] = 0.f;

#pragma unroll 5
    for (int k4 = 0; k4 < 25; k4++) {
        float4 tv = tr[k4];
        const float* tf = &tv.x;
#pragma unroll
        for (int kk = 0; kk < 4; kk++) {
            int k = k4 * 4 + kk;
            float4 w0 = *(const float4*)&W2s[k][0];
            float4 w1 = *(const float4*)&W2s[k][4];
            float4 w2 = *(const float4*)&W2s[k][8];
            float f = tf[kk];
            acc[0] = fmaf(f, w0.x, acc[0]);  acc[1] = fmaf(f, w0.y, acc[1]);
            acc[2] = fmaf(f, w0.z, acc[2]);  acc[3] = fmaf(f, w0.w, acc[3]);
            acc[4] = fmaf(f, w1.x, acc[4]);  acc[5] = fmaf(f, w1.y, acc[5]);
            acc[6] = fmaf(f, w1.z, acc[6]);  acc[7] = fmaf(f, w1.w, acc[7]);
            acc[8] = fmaf(f, w2.x, acc[8]);  acc[9] = fmaf(f, w2.y, acc[9]);
        }
    }
#pragma unroll
    for (int o = 0; o < N2; o++)
        g_z2t[((size_t)b * N2 + o) * T_STEPS + t] = acc[o];
}

// ---------------------------------------------------------------------------
// K4: layer-2 scan (exact round-9 version)
// ---------------------------------------------------------------------------
__global__ void __launch_bounds__(128, 1)
hh_layer2_kernel(float* __restrict__ out) {
    const int idx = blockIdx.x * 128 + threadIdx.x;
    if (idx >= BATCH * N2) return;
    const int b = idx / N2;
    const int o = idx - b * N2;

    const float* zl = g_z2t + (size_t)idx * T_STEPS;
    float* os = out + (size_t)b * T_STEPS * N2 + o;

    float V = -70.f, m = 0.f, n = 0.f, h = 1.f;
    os[0] = S0V;
    os += N2;

    float p0 = zl[0];
    float p1 = zl[1];
    float p2 = zl[2];
    float p3 = zl[3];
    zl += 4;

#pragma unroll 1
    for (int s4 = 0; s4 < 1996; s4 += 4) {
#pragma unroll
        for (int j = 0; j < 4; j++) {
            float zc = p0;
            p0 = p1; p1 = p2; p2 = p3; p3 = *zl; zl++;
            *os = hh_step_t(zc, V, m, n, h);
            os += N2;
        }
    }
#pragma unroll
    for (int j = 0; j < 3; j++) {
        float zc = p0;
        p0 = p1; p1 = p2; p2 = p3; p3 = *zl; zl++;
        *os = hh_step_t(zc, V, m, n, h);
        os += N2;
    }
}

// ---------------------------------------------------------------------------
extern "C" void kernel_launch(void* const* d_in, const int* in_sizes, int n_in,
                              void* d_out, int out_size) {
    const float* batch = (const float*)d_in[0];   // (100, 2000, 784)
    const float* W1    = (const float*)d_in[1];   // (100, 784)
    const float* W2    = (const float*)d_in[2];   // (10, 100)
    float* out = (float*)d_out;                   // (100, 2000, 10)

    w1_convert_kernel<<<(112 * K_DIM + 255) / 256, 256>>>(W1);
    fused_gemm_l1<<<BATCH + NCHUNKS, 256>>>(batch);
    z2_kernel<<<(M_ROWS + 255) / 256, 256>>>(W2);
    hh_layer2_kernel<<<(BATCH * N2 + 127) / 128, 128>>>(out);
}